// round 15
// baseline (speedup 1.0000x reference)
#include <cuda_runtime.h>
#include <math.h>

#define B_ 2
#define S_ 256
#define T_ 256
#define D_ 256
#define H_ 8
#define DH_ 32
#define DR_ 64
#define FF_ 1024
#define L_ 2
#define ROWS_S (B_*S_)   // 512
#define ROWS_T (B_*T_)   // 512
#define SRS 68           // smem rpe row stride (floats): 68*4B=272B, 16B aligned, conflict-free

// -------- scratch (static device allocations; no cudaMalloc allowed) --------
__device__ float g_s2 [ROWS_S*D_];
__device__ float g_tn [ROWS_T*D_];
__device__ float g_q  [ROWS_S*D_];
__device__ float g_k  [ROWS_T*D_];
__device__ float g_v  [ROWS_T*D_];
__device__ float g_qr [ROWS_S*H_*DR_];
__device__ float g_qbr[ROWS_S*H_];
__device__ float g_att[ROWS_S*D_];
__device__ float g_ff1[ROWS_S*FF_];

// ---------------------------------------------------------------------------
__global__ void copy_kernel(const float* __restrict__ in, float* __restrict__ out, int n) {
    int i = blockIdx.x * 256 + threadIdx.x;
    if (i < n) out[i] = in[i];
}

// one block (256 threads) per row; D_=256 exactly
__global__ __launch_bounds__(256) void ln_kernel(
    const float* __restrict__ x, const float* __restrict__ g,
    const float* __restrict__ b, float* __restrict__ y) {
    __shared__ float red[256];
    int row = blockIdx.x, tid = threadIdx.x;
    float v = x[row * D_ + tid];
    red[tid] = v; __syncthreads();
    #pragma unroll
    for (int s = 128; s > 0; s >>= 1) { if (tid < s) red[tid] += red[tid + s]; __syncthreads(); }
    float mean = red[0] * (1.0f / D_);
    __syncthreads();
    float d = v - mean;
    red[tid] = d * d; __syncthreads();
    #pragma unroll
    for (int s = 128; s > 0; s >>= 1) { if (tid < s) red[tid] += red[tid + s]; __syncthreads(); }
    float inv = rsqrtf(red[0] * (1.0f / D_) + 1e-5f);
    y[row * D_ + tid] = d * inv * g[tid] + b[tid];
}

// C[M,N] = A[M,K] @ W[K,N] + bias ( + relu ) ( + res ).  M,N,K divisible by 32.
__global__ __launch_bounds__(256) void gemm_kernel(
    const float* __restrict__ A, const float* __restrict__ W,
    const float* __restrict__ bias, const float* __restrict__ res,
    float* __restrict__ C, int M, int N, int K, int relu) {
    __shared__ float As[32][33];
    __shared__ float Ws[32][33];
    int tx = threadIdx.x, ty = threadIdx.y;          // 16x16
    int tid = ty * 16 + tx;
    int bm = blockIdx.y * 32, bn = blockIdx.x * 32;
    float acc00 = 0.f, acc01 = 0.f, acc10 = 0.f, acc11 = 0.f;
    for (int k0 = 0; k0 < K; k0 += 32) {
        #pragma unroll
        for (int i = 0; i < 4; i++) {
            int e = tid + i * 256;
            int r = e >> 5, c = e & 31;
            As[r][c] = A[(size_t)(bm + r) * K + k0 + c];
            Ws[r][c] = W[(size_t)(k0 + r) * N + bn + c];
        }
        __syncthreads();
        #pragma unroll
        for (int kk = 0; kk < 32; kk++) {
            float a0 = As[ty * 2][kk], a1 = As[ty * 2 + 1][kk];
            float w0 = Ws[kk][tx * 2], w1 = Ws[kk][tx * 2 + 1];
            acc00 += a0 * w0; acc01 += a0 * w1;
            acc10 += a1 * w0; acc11 += a1 * w1;
        }
        __syncthreads();
    }
    int r0 = bm + ty * 2, c0 = bn + tx * 2;
    float vals[2][2] = {{acc00, acc01}, {acc10, acc11}};
    #pragma unroll
    for (int i = 0; i < 2; i++)
        #pragma unroll
        for (int j = 0; j < 2; j++) {
            float v = vals[i][j] + bias[c0 + j];
            if (relu) v = fmaxf(v, 0.f);
            if (res)  v += res[(size_t)(r0 + i) * N + c0 + j];
            C[(size_t)(r0 + i) * N + c0 + j] = v;
        }
}

// qr[b,s,h,dr] = sum_dh q[b,s,h*32+dh] * wr[dr, h*32+dh];  qbr = q . br_k
__global__ __launch_bounds__(256) void qr_kernel(
    const float* __restrict__ q, const float* __restrict__ wr,
    const float* __restrict__ br, float* __restrict__ qr, float* __restrict__ qbr) {
    __shared__ float sq[D_];
    int row = blockIdx.x, tid = threadIdx.x;
    sq[tid] = q[(size_t)row * D_ + tid];
    __syncthreads();
    for (int o = tid; o < H_ * DR_; o += 256) {
        int h = o >> 6, dr = o & 63;
        float a = 0.f;
        const float* wrow = wr + (size_t)dr * (2 * D_) + h * DH_;
        const float* qh = sq + h * DH_;
        #pragma unroll
        for (int d = 0; d < DH_; d++) a += qh[d] * wrow[d];
        qr[(size_t)row * (H_ * DR_) + o] = a;
    }
    if (tid < H_) {
        float a = 0.f;
        const float* qh = sq + tid * DH_;
        const float* bh = br + tid * DH_;
        #pragma unroll
        for (int d = 0; d < DH_; d++) a += qh[d] * bh[d];
        qbr[row * H_ + tid] = a;
    }
}

// fused RPE attention: one CTA per (b,s) query row, 256 threads
__global__ __launch_bounds__(256) void attn_kernel(
    const float* __restrict__ q, const float* __restrict__ k,
    const float* __restrict__ v, const float* __restrict__ rpe,
    const float* __restrict__ qr, const float* __restrict__ qbr,
    const float* __restrict__ wr, const float* __restrict__ br,
    const int* __restrict__ tmask, float* __restrict__ out) {
    extern __shared__ float sm[];
    float* srpe = sm;                    // T_*SRS
    float* sq   = srpe + T_ * SRS;       // D_
    float* sqr  = sq + D_;               // H_*DR_
    float* sw   = sqr + H_ * DR_;        // H_*T_
    float* swr  = sw + H_ * T_;          // H_*DR_
    __shared__ float sqbr[H_];

    int bidx = blockIdx.x;
    int b = bidx >> 8;                   // / S_
    int tid = threadIdx.x;

    sq[tid] = q[(size_t)bidx * D_ + tid];
    for (int o = tid; o < H_ * DR_; o += 256) sqr[o] = qr[(size_t)bidx * H_ * DR_ + o];
    if (tid < H_) sqbr[tid] = qbr[bidx * H_ + tid];
    {
        const float4* rs = (const float4*)(rpe + (size_t)bidx * T_ * DR_);
        for (int o = tid; o < T_ * (DR_ / 4); o += 256) {
            int t = o >> 4, j = o & 15;
            ((float4*)(srpe + t * SRS))[j] = rs[o];
        }
    }
    __syncthreads();

    // --- scores: thread t computes all H heads for key column t ---
    {
        int t = tid;
        float rreg[DR_];
        const float4* r4 = (const float4*)(srpe + t * SRS);
        #pragma unroll
        for (int j = 0; j < 16; j++) {
            float4 rv = r4[j];
            rreg[4*j] = rv.x; rreg[4*j+1] = rv.y; rreg[4*j+2] = rv.z; rreg[4*j+3] = rv.w;
        }
        bool masked = tmask[b * T_ + t] != 0;
        const float scale = 0.17677669529663688f;   // 1/sqrt(32)
        const float4* k4 = (const float4*)(k + ((size_t)(b * T_ + t)) * D_);
        #pragma unroll
        for (int h = 0; h < H_; h++) {
            float qk = 0.f;
            #pragma unroll
            for (int j = 0; j < 8; j++) {
                float4 kv = k4[h * 8 + j];
                int base = h * DH_ + j * 4;
                qk += sq[base] * kv.x + sq[base+1] * kv.y + sq[base+2] * kv.z + sq[base+3] * kv.w;
            }
            float rq = 0.f;
            #pragma unroll
            for (int dr = 0; dr < DR_; dr++) rq += rreg[dr] * sqr[h * DR_ + dr];
            float sc = (qk + rq + sqbr[h]) * scale;
            sw[h * T_ + t] = masked ? -1e30f : sc;
        }
    }
    __syncthreads();

    // --- softmax: warp h handles head h over T_=256 ---
    {
        int h = tid >> 5, lane = tid & 31;
        float* row = sw + h * T_;
        float vals[8]; float m = -1e30f;
        #pragma unroll
        for (int j = 0; j < 8; j++) { vals[j] = row[lane + 32 * j]; m = fmaxf(m, vals[j]); }
        #pragma unroll
        for (int off = 16; off; off >>= 1) m = fmaxf(m, __shfl_xor_sync(0xffffffffu, m, off));
        float sum = 0.f;
        #pragma unroll
        for (int j = 0; j < 8; j++) { vals[j] = __expf(vals[j] - m); sum += vals[j]; }
        #pragma unroll
        for (int off = 16; off; off >>= 1) sum += __shfl_xor_sync(0xffffffffu, sum, off);
        float inv = 1.f / sum;
        #pragma unroll
        for (int j = 0; j < 8; j++) row[lane + 32 * j] = vals[j] * inv;
    }
    __syncthreads();

    // --- out_v[d] = sum_t w[h][t] * v[b,t,d]  (coalesced v reads) ---
    float accv = 0.f;
    {
        int d = tid, h = d >> 5;
        const float* wrow = sw + h * T_;
        const float* vb = v + (size_t)b * T_ * D_ + d;
        #pragma unroll 4
        for (int t = 0; t < T_; t++) accv += wrow[t] * vb[(size_t)t * D_];
    }
    // --- wrpe[h,dr] = sum_t w[h][t] * rpe[t,dr] ---
    for (int o = tid; o < H_ * DR_; o += 256) {
        int h = o >> 6, dr = o & 63;
        const float* wrow = sw + h * T_;
        float a = 0.f;
        #pragma unroll 4
        for (int t = 0; t < T_; t++) a += wrow[t] * srpe[t * SRS + dr];
        swr[o] = a;
    }
    __syncthreads();
    // --- out[d] = out_v + wrpe[h] @ wr_v[:, d] + br_v[d]  (sum_t w == 1) ---
    {
        int d = tid, h = d >> 5;
        float a = br[D_ + d];
        const float* wcol = wr + D_ + d;          // wr[dr][D_+d], stride 2*D_
        #pragma unroll
        for (int dr = 0; dr < DR_; dr++) a += swr[h * DR_ + dr] * wcol[(size_t)dr * 2 * D_];
        out[(size_t)bidx * D_ + d] = accv + a;
    }
}

__global__ void mask_kernel(float* __restrict__ x, const int* __restrict__ mask) {
    int i = blockIdx.x * 256 + threadIdx.x;
    if (i < ROWS_S * D_ && mask[i >> 8] != 0) x[i] = 0.f;
}

// ---------------------------------------------------------------------------
extern "C" void kernel_launch(void* const* d_in, const int* in_sizes, int n_in,
                              void* d_out, int out_size) {
    const float* src   = (const float*)d_in[0];
    const float* tgt   = (const float*)d_in[1];
    const float* rpe   = (const float*)d_in[2];
    const int*   smask = (const int*)  d_in[3];
    const int*   tmask = (const int*)  d_in[4];
    const float* ln1_g = (const float*)d_in[5];
    const float* ln1_b = (const float*)d_in[6];
    const float* lnt_g = (const float*)d_in[7];
    const float* lnt_b = (const float*)d_in[8];
    const float* ln2_g = (const float*)d_in[9];
    const float* ln2_b = (const float*)d_in[10];
    const float* wq = (const float*)d_in[11];
    const float* bq = (const float*)d_in[12];
    const float* wk = (const float*)d_in[13];
    const float* bk = (const float*)d_in[14];
    const float* wv = (const float*)d_in[15];
    const float* bv = (const float*)d_in[16];
    const float* wo = (const float*)d_in[17];
    const float* bo = (const float*)d_in[18];
    const float* wr = (const float*)d_in[19];
    const float* br = (const float*)d_in[20];
    const float* w1 = (const float*)d_in[21];
    const float* b1 = (const float*)d_in[22];
    const float* w2 = (const float*)d_in[23];
    const float* b2 = (const float*)d_in[24];
    float* out = (float*)d_out;

    const int ATTN_SMEM = (T_ * SRS + D_ + H_ * DR_ + H_ * T_ + H_ * DR_) * 4; // 82944 B
    cudaFuncSetAttribute(attn_kernel, cudaFuncAttributeMaxDynamicSharedMemorySize, ATTN_SMEM);

    copy_kernel<<<(ROWS_S * D_ + 255) / 256, 256>>>(src, out, ROWS_S * D_);

    dim3 blk(16, 16);
    for (int i = 0; i < L_; i++) {
        ln_kernel<<<ROWS_S, 256>>>(out, ln1_g + i * D_, ln1_b + i * D_, g_s2);
        ln_kernel<<<ROWS_T, 256>>>(tgt, lnt_g + i * D_, lnt_b + i * D_, g_tn);

        gemm_kernel<<<dim3(D_ / 32, ROWS_S / 32), blk>>>(
            g_s2, wq + (size_t)i * D_ * D_, bq + i * D_, nullptr, g_q, ROWS_S, D_, D_, 0);
        gemm_kernel<<<dim3(D_ / 32, ROWS_T / 32), blk>>>(
            g_tn, wk + (size_t)i * D_ * D_, bk + i * D_, nullptr, g_k, ROWS_T, D_, D_, 0);
        gemm_kernel<<<dim3(D_ / 32, ROWS_T / 32), blk>>>(
            g_tn, wv + (size_t)i * D_ * D_, bv + i * D_, nullptr, g_v, ROWS_T, D_, D_, 0);

        qr_kernel<<<ROWS_S, 256>>>(g_q, wr + (size_t)i * DR_ * 2 * D_, br + i * 2 * D_, g_qr, g_qbr);

        attn_kernel<<<ROWS_S, 256, ATTN_SMEM>>>(
            g_q, g_k, g_v, rpe, g_qr, g_qbr,
            wr + (size_t)i * DR_ * 2 * D_, br + i * 2 * D_, tmask, g_att);

        gemm_kernel<<<dim3(D_ / 32, ROWS_S / 32), blk>>>(
            g_att, wo + (size_t)i * D_ * D_, bo + i * D_, out, out, ROWS_S, D_, D_, 0);

        ln_kernel<<<ROWS_S, 256>>>(out, ln2_g + i * D_, ln2_b + i * D_, g_s2);

        gemm_kernel<<<dim3(FF_ / 32, ROWS_S / 32), blk>>>(
            g_s2, w1 + (size_t)i * D_ * FF_, b1 + i * FF_, nullptr, g_ff1, ROWS_S, FF_, D_, 1);
        gemm_kernel<<<dim3(D_ / 32, ROWS_S / 32), blk>>>(
            g_ff1, w2 + (size_t)i * FF_ * D_, b2 + i * D_, out, out, ROWS_S, D_, FF_, 0);

        mask_kernel<<<(ROWS_S * D_ + 255) / 256, 256>>>(out, smask);
    }
}

// round 16
// speedup vs baseline: 1.0050x; 1.0050x over previous
#include <cuda_runtime.h>
#include <math.h>

#define B_ 2
#define S_ 256
#define T_ 256
#define D_ 256
#define H_ 8
#define DH_ 32
#define DR_ 64
#define FF_ 1024
#define L_ 2
#define ROWS_S (B_*S_)   // 512
#define ROWS_T (B_*T_)   // 512
#define SRS 68           // smem rpe row stride (floats): 68*4B=272B, 16B aligned, conflict-free

// -------- scratch (static device allocations; no cudaMalloc allowed) --------
__device__ float g_s2 [ROWS_S*D_];
__device__ float g_tn [ROWS_T*D_];
__device__ float g_q  [ROWS_S*D_];
__device__ float g_k  [ROWS_T*D_];
__device__ float g_v  [ROWS_T*D_];
__device__ float g_qr [ROWS_S*H_*DR_];
__device__ float g_qbr[ROWS_S*H_];
__device__ float g_att[ROWS_S*D_];
__device__ float g_ff1[ROWS_S*FF_];

// ---------------------------------------------------------------------------
__global__ void copy_kernel(const float* __restrict__ in, float* __restrict__ out, int n) {
    int i = blockIdx.x * 256 + threadIdx.x;
    if (i < n) out[i] = in[i];
}

// one block (256 threads) per row; D_=256 exactly
__global__ __launch_bounds__(256) void ln_kernel(
    const float* __restrict__ x, const float* __restrict__ g,
    const float* __restrict__ b, float* __restrict__ y) {
    __shared__ float red[256];
    int row = blockIdx.x, tid = threadIdx.x;
    float v = x[row * D_ + tid];
    red[tid] = v; __syncthreads();
    #pragma unroll
    for (int s = 128; s > 0; s >>= 1) { if (tid < s) red[tid] += red[tid + s]; __syncthreads(); }
    float mean = red[0] * (1.0f / D_);
    __syncthreads();
    float d = v - mean;
    red[tid] = d * d; __syncthreads();
    #pragma unroll
    for (int s = 128; s > 0; s >>= 1) { if (tid < s) red[tid] += red[tid + s]; __syncthreads(); }
    float inv = rsqrtf(red[0] * (1.0f / D_) + 1e-5f);
    y[row * D_ + tid] = d * inv * g[tid] + b[tid];
}

// C[M,N] = A[M,K] @ W[K,N] + bias ( + relu ) ( + res ).  M,N,K divisible by 32.
__global__ __launch_bounds__(256) void gemm_kernel(
    const float* __restrict__ A, const float* __restrict__ W,
    const float* __restrict__ bias, const float* __restrict__ res,
    float* __restrict__ C, int M, int N, int K, int relu) {
    __shared__ float As[32][33];
    __shared__ float Ws[32][33];
    int tx = threadIdx.x, ty = threadIdx.y;          // 16x16
    int tid = ty * 16 + tx;
    int bm = blockIdx.y * 32, bn = blockIdx.x * 32;
    float acc00 = 0.f, acc01 = 0.f, acc10 = 0.f, acc11 = 0.f;
    for (int k0 = 0; k0 < K; k0 += 32) {
        #pragma unroll
        for (int i = 0; i < 4; i++) {
            int e = tid + i * 256;
            int r = e >> 5, c = e & 31;
            As[r][c] = A[(size_t)(bm + r) * K + k0 + c];
            Ws[r][c] = W[(size_t)(k0 + r) * N + bn + c];
        }
        __syncthreads();
        #pragma unroll
        for (int kk = 0; kk < 32; kk++) {
            float a0 = As[ty * 2][kk], a1 = As[ty * 2 + 1][kk];
            float w0 = Ws[kk][tx * 2], w1 = Ws[kk][tx * 2 + 1];
            acc00 += a0 * w0; acc01 += a0 * w1;
            acc10 += a1 * w0; acc11 += a1 * w1;
        }
        __syncthreads();
    }
    int r0 = bm + ty * 2, c0 = bn + tx * 2;
    float vals[2][2] = {{acc00, acc01}, {acc10, acc11}};
    #pragma unroll
    for (int i = 0; i < 2; i++)
        #pragma unroll
        for (int j = 0; j < 2; j++) {
            float v = vals[i][j] + bias[c0 + j];
            if (relu) v = fmaxf(v, 0.f);
            if (res)  v += res[(size_t)(r0 + i) * N + c0 + j];
            C[(size_t)(r0 + i) * N + c0 + j] = v;
        }
}

// qr[b,s,h,dr] = sum_dh q[b,s,h*32+dh] * wr[dr, h*32+dh];  qbr = q . br_k
__global__ __launch_bounds__(256) void qr_kernel(
    const float* __restrict__ q, const float* __restrict__ wr,
    const float* __restrict__ br, float* __restrict__ qr, float* __restrict__ qbr) {
    __shared__ float sq[D_];
    int row = blockIdx.x, tid = threadIdx.x;
    sq[tid] = q[(size_t)row * D_ + tid];
    __syncthreads();
    for (int o = tid; o < H_ * DR_; o += 256) {
        int h = o >> 6, dr = o & 63;
        float a = 0.f;
        const float* wrow = wr + (size_t)dr * (2 * D_) + h * DH_;
        const float* qh = sq + h * DH_;
        #pragma unroll
        for (int d = 0; d < DH_; d++) a += qh[d] * wrow[d];
        qr[(size_t)row * (H_ * DR_) + o] = a;
    }
    if (tid < H_) {
        float a = 0.f;
        const float* qh = sq + tid * DH_;
        const float* bh = br + tid * DH_;
        #pragma unroll
        for (int d = 0; d < DH_; d++) a += qh[d] * bh[d];
        qbr[row * H_ + tid] = a;
    }
}

// fused RPE attention: one CTA per (b,s) query row, 256 threads
__global__ __launch_bounds__(256) void attn_kernel(
    const float* __restrict__ q, const float* __restrict__ k,
    const float* __restrict__ v, const float* __restrict__ rpe,
    const float* __restrict__ qr, const float* __restrict__ qbr,
    const float* __restrict__ wr, const float* __restrict__ br,
    const int* __restrict__ tmask, float* __restrict__ out) {
    extern __shared__ float sm[];
    float* srpe = sm;                    // T_*SRS
    float* sq   = srpe + T_ * SRS;       // D_
    float* sqr  = sq + D_;               // H_*DR_
    float* sw   = sqr + H_ * DR_;        // H_*T_
    float* swr  = sw + H_ * T_;          // H_*DR_
    __shared__ float sqbr[H_];

    int bidx = blockIdx.x;
    int b = bidx >> 8;                   // / S_
    int tid = threadIdx.x;

    sq[tid] = q[(size_t)bidx * D_ + tid];
    for (int o = tid; o < H_ * DR_; o += 256) sqr[o] = qr[(size_t)bidx * H_ * DR_ + o];
    if (tid < H_) sqbr[tid] = qbr[bidx * H_ + tid];
    {
        const float4* rs = (const float4*)(rpe + (size_t)bidx * T_ * DR_);
        for (int o = tid; o < T_ * (DR_ / 4); o += 256) {
            int t = o >> 4, j = o & 15;
            ((float4*)(srpe + t * SRS))[j] = rs[o];
        }
    }
    __syncthreads();

    // --- scores: thread t computes all H heads for key column t ---
    {
        int t = tid;
        float rreg[DR_];
        const float4* r4 = (const float4*)(srpe + t * SRS);
        #pragma unroll
        for (int j = 0; j < 16; j++) {
            float4 rv = r4[j];
            rreg[4*j] = rv.x; rreg[4*j+1] = rv.y; rreg[4*j+2] = rv.z; rreg[4*j+3] = rv.w;
        }
        bool masked = tmask[b * T_ + t] != 0;
        const float scale = 0.17677669529663688f;   // 1/sqrt(32)
        const float4* k4 = (const float4*)(k + ((size_t)(b * T_ + t)) * D_);
        #pragma unroll
        for (int h = 0; h < H_; h++) {
            float qk = 0.f;
            #pragma unroll
            for (int j = 0; j < 8; j++) {
                float4 kv = k4[h * 8 + j];
                int base = h * DH_ + j * 4;
                qk += sq[base] * kv.x + sq[base+1] * kv.y + sq[base+2] * kv.z + sq[base+3] * kv.w;
            }
            float rq = 0.f;
            #pragma unroll
            for (int dr = 0; dr < DR_; dr++) rq += rreg[dr] * sqr[h * DR_ + dr];
            float sc = (qk + rq + sqbr[h]) * scale;
            sw[h * T_ + t] = masked ? -1e30f : sc;
        }
    }
    __syncthreads();

    // --- softmax: warp h handles head h over T_=256 ---
    {
        int h = tid >> 5, lane = tid & 31;
        float* row = sw + h * T_;
        float vals[8]; float m = -1e30f;
        #pragma unroll
        for (int j = 0; j < 8; j++) { vals[j] = row[lane + 32 * j]; m = fmaxf(m, vals[j]); }
        #pragma unroll
        for (int off = 16; off; off >>= 1) m = fmaxf(m, __shfl_xor_sync(0xffffffffu, m, off));
        float sum = 0.f;
        #pragma unroll
        for (int j = 0; j < 8; j++) { vals[j] = __expf(vals[j] - m); sum += vals[j]; }
        #pragma unroll
        for (int off = 16; off; off >>= 1) sum += __shfl_xor_sync(0xffffffffu, sum, off);
        float inv = 1.f / sum;
        #pragma unroll
        for (int j = 0; j < 8; j++) row[lane + 32 * j] = vals[j] * inv;
    }
    __syncthreads();

    // --- out_v[d] = sum_t w[h][t] * v[b,t,d]  (coalesced v reads) ---
    float accv = 0.f;
    {
        int d = tid, h = d >> 5;
        const float* wrow = sw + h * T_;
        const float* vb = v + (size_t)b * T_ * D_ + d;
        #pragma unroll 4
        for (int t = 0; t < T_; t++) accv += wrow[t] * vb[(size_t)t * D_];
    }
    // --- wrpe[h,dr] = sum_t w[h][t] * rpe[t,dr] ---
    for (int o = tid; o < H_ * DR_; o += 256) {
        int h = o >> 6, dr = o & 63;
        const float* wrow = sw + h * T_;
        float a = 0.f;
        #pragma unroll 4
        for (int t = 0; t < T_; t++) a += wrow[t] * srpe[t * SRS + dr];
        swr[o] = a;
    }
    __syncthreads();
    // --- out[d] = out_v + wrpe[h] @ wr_v[:, d] + br_v[d]  (sum_t w == 1) ---
    {
        int d = tid, h = d >> 5;
        float a = br[D_ + d];
        const float* wcol = wr + D_ + d;          // wr[dr][D_+d], stride 2*D_
        #pragma unroll
        for (int dr = 0; dr < DR_; dr++) a += swr[h * DR_ + dr] * wcol[(size_t)dr * 2 * D_];
        out[(size_t)bidx * D_ + d] = accv + a;
    }
}

__global__ void mask_kernel(float* __restrict__ x, const int* __restrict__ mask) {
    int i = blockIdx.x * 256 + threadIdx.x;
    if (i < ROWS_S * D_ && mask[i >> 8] != 0) x[i] = 0.f;
}

// ---------------------------------------------------------------------------
extern "C" void kernel_launch(void* const* d_in, const int* in_sizes, int n_in,
                              void* d_out, int out_size) {
    const float* src   = (const float*)d_in[0];
    const float* tgt   = (const float*)d_in[1];
    const float* rpe   = (const float*)d_in[2];
    const int*   smask = (const int*)  d_in[3];
    const int*   tmask = (const int*)  d_in[4];
    const float* ln1_g = (const float*)d_in[5];
    const float* ln1_b = (const float*)d_in[6];
    const float* lnt_g = (const float*)d_in[7];
    const float* lnt_b = (const float*)d_in[8];
    const float* ln2_g = (const float*)d_in[9];
    const float* ln2_b = (const float*)d_in[10];
    const float* wq = (const float*)d_in[11];
    const float* bq = (const float*)d_in[12];
    const float* wk = (const float*)d_in[13];
    const float* bk = (const float*)d_in[14];
    const float* wv = (const float*)d_in[15];
    const float* bv = (const float*)d_in[16];
    const float* wo = (const float*)d_in[17];
    const float* bo = (const float*)d_in[18];
    const float* wr = (const float*)d_in[19];
    const float* br = (const float*)d_in[20];
    const float* w1 = (const float*)d_in[21];
    const float* b1 = (const float*)d_in[22];
    const float* w2 = (const float*)d_in[23];
    const float* b2 = (const float*)d_in[24];
    float* out = (float*)d_out;

    const int ATTN_SMEM = (T_ * SRS + D_ + H_ * DR_ + H_ * T_ + H_ * DR_) * 4; // 82944 B
    cudaFuncSetAttribute(attn_kernel, cudaFuncAttributeMaxDynamicSharedMemorySize, ATTN_SMEM);

    copy_kernel<<<(ROWS_S * D_ + 255) / 256, 256>>>(src, out, ROWS_S * D_);

    dim3 blk(16, 16);
    for (int i = 0; i < L_; i++) {
        ln_kernel<<<ROWS_S, 256>>>(out, ln1_g + i * D_, ln1_b + i * D_, g_s2);
        ln_kernel<<<ROWS_T, 256>>>(tgt, lnt_g + i * D_, lnt_b + i * D_, g_tn);

        gemm_kernel<<<dim3(D_ / 32, ROWS_S / 32), blk>>>(
            g_s2, wq + (size_t)i * D_ * D_, bq + i * D_, nullptr, g_q, ROWS_S, D_, D_, 0);
        gemm_kernel<<<dim3(D_ / 32, ROWS_T / 32), blk>>>(
            g_tn, wk + (size_t)i * D_ * D_, bk + i * D_, nullptr, g_k, ROWS_T, D_, D_, 0);
        gemm_kernel<<<dim3(D_ / 32, ROWS_T / 32), blk>>>(
            g_tn, wv + (size_t)i * D_ * D_, bv + i * D_, nullptr, g_v, ROWS_T, D_, D_, 0);

        qr_kernel<<<ROWS_S, 256>>>(g_q, wr + (size_t)i * DR_ * 2 * D_, br + i * 2 * D_, g_qr, g_qbr);

        attn_kernel<<<ROWS_S, 256, ATTN_SMEM>>>(
            g_q, g_k, g_v, rpe, g_qr, g_qbr,
            wr + (size_t)i * DR_ * 2 * D_, br + i * 2 * D_, tmask, g_att);

        gemm_kernel<<<dim3(D_ / 32, ROWS_S / 32), blk>>>(
            g_att, wo + (size_t)i * D_ * D_, bo + i * D_, out, out, ROWS_S, D_, D_, 0);

        ln_kernel<<<ROWS_S, 256>>>(out, ln2_g + i * D_, ln2_b + i * D_, g_s2);

        gemm_kernel<<<dim3(FF_ / 32, ROWS_S / 32), blk>>>(
            g_s2, w1 + (size_t)i * D_ * FF_, b1 + i * FF_, nullptr, g_ff1, ROWS_S, FF_, D_, 1);
        gemm_kernel<<<dim3(D_ / 32, ROWS_S / 32), blk>>>(
            g_ff1, w2 + (size_t)i * FF_ * D_, b2 + i * D_, out, out, ROWS_S, D_, FF_, 0);

        mask_kernel<<<(ROWS_S * D_ + 255) / 256, 256>>>(out, smask);
    }
}